// round 4
// baseline (speedup 1.0000x reference)
#include <cuda_runtime.h>
#include <cuda_fp16.h>

#define NN 50000
#define NE 800000
#define FEAT 128
#define HID 64
#define NCLS 12

#define NBLK 120          // persistent build kernel: <= SM count, co-resident
#define NTHR 1024
#define CHUNK ((NN + NBLK - 1) / NBLK)   // 417 nodes per block

// ---------------- scratch (static device globals; zero-initialized) ----------
__device__ __align__(16) int     g_deg[NN];        // zero invariant (reset by agg2)
__device__ __align__(16) int     g_bar[8];         // barrier counters (reset by agg2)
__device__ __align__(16) int     g_rowptr[NN + 1];
__device__ __align__(16) int     g_cursor[NN];
__device__ __align__(16) int     g_partial[NBLK];
__device__ __align__(16) int     g_pbase[NBLK];
__device__ __align__(16) int     g_csr[NE];
__device__ __align__(16) float   g_dinv[NN];
__device__ __align__(16) __half2 g_xws[NN * (HID / 2)];  // (A@W)*dinv fp16, 128B/row
__device__ __align__(16) float   g_h1[NN * HID];         // layer-1 activations

// ---------------- grid barrier (monotonic counter, co-resident grid) ---------
__device__ __forceinline__ void gbar(int idx) {
    __syncthreads();
    if (threadIdx.x == 0) {
        __threadfence();
        atomicAdd(&g_bar[idx], 1);
        while (atomicAdd(&g_bar[idx], 0) < NBLK) { }
    }
    __syncthreads();
}

// exclusive block scan over 1024 values (shfl warp scans + smem), 32-int smem
__device__ __forceinline__ int block_excl_scan(int v, int* sm32) {
    __syncthreads();                       // protect smem reuse
    int lane = threadIdx.x & 31, wid = threadIdx.x >> 5;
    int incl = v;
#pragma unroll
    for (int d = 1; d < 32; d <<= 1) {
        int n = __shfl_up_sync(0xffffffffu, incl, d);
        if (lane >= d) incl += n;
    }
    if (lane == 31) sm32[wid] = incl;
    __syncthreads();
    if (wid == 0) {
        int w = sm32[lane];
#pragma unroll
        for (int d = 1; d < 32; d <<= 1) {
            int n = __shfl_up_sync(0xffffffffu, w, d);
            if (lane >= d) w += n;
        }
        sm32[lane] = w;
    }
    __syncthreads();
    int off = wid ? sm32[wid - 1] : 0;
    return incl - v + off;
}

// ---------------- persistent CSR build: count -> scan -> fill ----------------
__global__ void __launch_bounds__(NTHR, 1)
k_build(const int* __restrict__ src, const int* __restrict__ dst) {
    __shared__ int sm32[32];
    int tid = threadIdx.x, b = blockIdx.x;
    int gt = b * NTHR + tid, gsz = NBLK * NTHR;

    // P1: degree count (g_deg is zero on entry — invariant)
    for (int e = gt; e < NE; e += gsz) atomicAdd(&g_deg[dst[e]], 1);
    gbar(0);

    // P2a: per-block chunk scan; thread tid holds deg of node base+tid
    int base = b * CHUNK;
    int i = base + tid;
    int v = (tid < CHUNK && i < NN) ? g_deg[i] : 0;
    int excl = block_excl_scan(v, sm32);
    if (tid == NTHR - 1) g_partial[b] = excl + v;   // block total
    gbar(1);

    // P2b: block 0 exclusive-scans the 120 block totals
    if (b == 0) {
        int p = (tid < NBLK) ? g_partial[tid] : 0;
        int pe = block_excl_scan(p, sm32);
        if (tid < NBLK) g_pbase[tid] = pe;
    }
    gbar(2);

    // P2c: finalize rowptr / cursor / dinv
    if (tid < CHUNK && i < NN) {
        int run = g_pbase[b] + excl;
        g_rowptr[i] = run;
        g_cursor[i] = run;
        g_dinv[i]   = rsqrtf((float)v + 1.0f);
    }
    if (b == 0 && tid == 0) g_rowptr[NN] = NE;
    gbar(3);

    // P3: fill CSR
    for (int e = gt; e < NE; e += gsz) {
        int d = dst[e];
        int pos = atomicAdd(&g_cursor[d], 1);
        g_csr[pos] = src[e];
    }
}

// ---------------- GEMM: C = (A @ W) * dinv[row] -> g_xws (fp16) -------------
template <int K, bool A_FROM_H1>
__global__ void k_gemm(const float* __restrict__ Aext, const float* __restrict__ W) {
    const int KB = 64;
    __shared__ float As[64][KB + 4];
    __shared__ float Ws[KB][HID];
    const float* A = A_FROM_H1 ? (const float*)g_h1 : Aext;
    int tid = threadIdx.x;
    int tx = tid & 15;      // 4 output cols
    int ty = tid >> 4;      // 4 output rows
    int row0 = blockIdx.x * 64;
    float acc[4][4] = {};
    for (int kb = 0; kb < K; kb += KB) {
        for (int i = tid; i < 64 * (KB / 4); i += 256) {
            int r  = i >> 4;
            int c4 = i & 15;
            float4 v = make_float4(0.f, 0.f, 0.f, 0.f);
            int gr = row0 + r;
            if (gr < NN) v = *(const float4*)&A[gr * K + kb + c4 * 4];
            *(float4*)&As[r][c4 * 4] = v;
        }
        for (int i = tid; i < KB * (HID / 4); i += 256) {
            int r  = i >> 4;
            int c4 = i & 15;
            *(float4*)&Ws[r][c4 * 4] = *(const float4*)&W[(kb + r) * HID + c4 * 4];
        }
        __syncthreads();
#pragma unroll 8
        for (int k = 0; k < KB; k++) {
            float a0 = As[ty * 4 + 0][k];
            float a1 = As[ty * 4 + 1][k];
            float a2 = As[ty * 4 + 2][k];
            float a3 = As[ty * 4 + 3][k];
            float4 w = *(const float4*)&Ws[k][tx * 4];
            acc[0][0] += a0 * w.x; acc[0][1] += a0 * w.y; acc[0][2] += a0 * w.z; acc[0][3] += a0 * w.w;
            acc[1][0] += a1 * w.x; acc[1][1] += a1 * w.y; acc[1][2] += a1 * w.z; acc[1][3] += a1 * w.w;
            acc[2][0] += a2 * w.x; acc[2][1] += a2 * w.y; acc[2][2] += a2 * w.z; acc[2][3] += a2 * w.w;
            acc[3][0] += a3 * w.x; acc[3][1] += a3 * w.y; acc[3][2] += a3 * w.z; acc[3][3] += a3 * w.w;
        }
        __syncthreads();
    }
#pragma unroll
    for (int i = 0; i < 4; i++) {
        int r = row0 + ty * 4 + i;
        if (r < NN) {
            float sc = g_dinv[r];
            __half2 h[2];
            h[0] = __floats2half2_rn(acc[i][0] * sc, acc[i][1] * sc);
            h[1] = __floats2half2_rn(acc[i][2] * sc, acc[i][3] * sc);
            *(uint2*)&g_xws[r * (HID / 2) + tx * 2] = *(uint2*)h;
        }
    }
}

// ---------------- aggregation: warp per dst node ----------------------------
__device__ __forceinline__ void agg_row(int node, int lane, float& a0, float& a1) {
    int beg = g_rowptr[node];
    int end = g_rowptr[node + 1];
    a0 = 0.f; a1 = 0.f;
    for (int base = beg; base < end; base += 32) {
        int idx = base + lane;
        int s_l = (idx < end) ? g_csr[idx] : 0;
        int iters = end - base;
        if (iters > 32) iters = 32;
#pragma unroll 4
        for (int j = 0; j < iters; j++) {
            int s = __shfl_sync(0xffffffffu, s_l, j);
            float2 v = __half22float2(g_xws[s * (HID / 2) + lane]);
            a0 += v.x;
            a1 += v.y;
        }
    }
}

__global__ void k_agg1(const float* __restrict__ b1) {
    int warp = (blockIdx.x * blockDim.x + threadIdx.x) >> 5;
    int lane = threadIdx.x & 31;
    if (warp >= NN) return;
    float a0, a1;
    agg_row(warp, lane, a0, a1);
    float dd = g_dinv[warp];
    float2 sv = __half22float2(g_xws[warp * (HID / 2) + lane]);
    float r0 = fmaxf(fmaf(dd, a0 + sv.x, b1[2 * lane + 0]), 0.f);
    float r1 = fmaxf(fmaf(dd, a1 + sv.y, b1[2 * lane + 1]), 0.f);
    *(float2*)&g_h1[warp * HID + 2 * lane] = make_float2(r0, r1);
}

// layer-2 aggregation fused with 64->12 FC + bfc; also resets invariants.
__global__ void k_agg2(const float* __restrict__ b2, const float* __restrict__ Wfc,
                       const float* __restrict__ bfc, float* __restrict__ out) {
    __shared__ float sW[HID * NCLS];
    __shared__ float sb2[HID];
    __shared__ float sbfc[NCLS];
    int tid = threadIdx.x;
    for (int i = tid; i < HID * NCLS; i += 256) sW[i] = Wfc[i];
    if (tid < HID)  sb2[tid]  = b2[tid];
    if (tid < NCLS) sbfc[tid] = bfc[tid];
    __syncthreads();

    // maintain invariants for next launch: deg + barrier counters back to zero
    int gt = blockIdx.x * blockDim.x + tid;
    if (gt < NN) g_deg[gt] = 0;
    if (gt < 8)  g_bar[gt] = 0;

    int warp = gt >> 5;
    int lane = tid & 31;
    if (warp >= NN) return;
    float a0, a1;
    agg_row(warp, lane, a0, a1);
    float dd = g_dinv[warp];
    float2 sv = __half22float2(g_xws[warp * (HID / 2) + lane]);
    float t0 = fmaxf(fmaf(dd, a0 + sv.x, sb2[2 * lane + 0]), 0.f);
    float t1 = fmaxf(fmaf(dd, a1 + sv.y, sb2[2 * lane + 1]), 0.f);

    float res = 0.f;
#pragma unroll
    for (int c = 0; c < NCLS; c++) {
        float p = t0 * sW[(2 * lane + 0) * NCLS + c] + t1 * sW[(2 * lane + 1) * NCLS + c];
        p += __shfl_xor_sync(0xffffffffu, p, 16);
        p += __shfl_xor_sync(0xffffffffu, p, 8);
        p += __shfl_xor_sync(0xffffffffu, p, 4);
        p += __shfl_xor_sync(0xffffffffu, p, 2);
        p += __shfl_xor_sync(0xffffffffu, p, 1);
        if (lane == c) res = p + sbfc[c];
    }
    if (lane < NCLS) out[warp * NCLS + lane] = res;
}

// ---------------- launch -----------------------------------------------------
extern "C" void kernel_launch(void* const* d_in, const int* in_sizes, int n_in,
                              void* d_out, int out_size) {
    const float* x   = (const float*)d_in[0];
    const int*   ei  = (const int*)d_in[1];   // int32 (JAX x64-disabled)
    const float* W1  = (const float*)d_in[2];
    const float* b1  = (const float*)d_in[3];
    const float* W2  = (const float*)d_in[4];
    const float* b2  = (const float*)d_in[5];
    const float* Wfc = (const float*)d_in[6];
    const float* bfc = (const float*)d_in[7];
    float* out = (float*)d_out;
    const int* srcp = ei;
    const int* dstp = ei + NE;

    k_build<<<NBLK, NTHR>>>(srcp, dstp);                      // CSR + dinv
    k_gemm<FEAT, false><<<(NN + 63) / 64, 256>>>(x, W1);      // -> g_xws (fp16)
    k_agg1<<<(NN + 7) / 8, 256>>>(b1);                         // -> g_h1
    k_gemm<HID, true><<<(NN + 63) / 64, 256>>>(nullptr, W2);   // -> g_xws (fp16)
    k_agg2<<<(NN + 7) / 8, 256>>>(b2, Wfc, bfc, out);          // -> d_out + reset
}

// round 5
// speedup vs baseline: 1.1854x; 1.1854x over previous
#include <cuda_runtime.h>
#include <cuda_fp16.h>

#define NN 50000
#define NE 800000
#define FEAT 128
#define HID 64
#define NCLS 12
#define SCAN_CHUNK 1024
#define NB ((NN + SCAN_CHUNK - 1) / SCAN_CHUNK)   // 49

// ---------------- scratch (static device globals) ----------------------------
__device__ __align__(16) int     g_deg[NN];
__device__ __align__(16) int     g_rowptr[NN + 1];
__device__ __align__(16) int     g_cursor[NN];
__device__ __align__(16) int     g_partial[NB + 8];
__device__ __align__(16) int     g_csr[NE];
__device__ __align__(16) float   g_dinv[NN];
__device__ __align__(16) __half2 g_xws[NN * (HID / 2)];  // (A@W)*dinv fp16, 128B/row
__device__ __align__(16) __half2 g_h1[NN * (HID / 2)];   // layer-1 activations (fp16)

// ---------------- CSR build (R3 chain) ---------------------------------------
__global__ void k_zero_deg() {
    int i = blockIdx.x * blockDim.x + threadIdx.x;
    if (i < NN) g_deg[i] = 0;
}

__global__ void k_count(const int* __restrict__ dst) {
    int e = blockIdx.x * blockDim.x + threadIdx.x;
    if (e < NE) atomicAdd(&g_deg[dst[e]], 1);
}

__global__ void k_scan1() {
    __shared__ int wsum[8];
    int t = threadIdx.x, b = blockIdx.x;
    int base = b * SCAN_CHUNK + t * 4;
    int s = 0;
#pragma unroll
    for (int i = 0; i < 4; i++)
        if (base + i < NN) s += g_deg[base + i];
#pragma unroll
    for (int d = 16; d; d >>= 1) s += __shfl_xor_sync(0xffffffffu, s, d);
    if ((t & 31) == 0) wsum[t >> 5] = s;
    __syncthreads();
    if (t == 0) {
        int tot = 0;
#pragma unroll
        for (int i = 0; i < 8; i++) tot += wsum[i];
        g_partial[b] = tot;
    }
}

__global__ void k_scan2() {
    __shared__ int w0sum;
    int t = threadIdx.x;               // 64 threads
    int lane = t & 31, wid = t >> 5;
    int v = (t < NB) ? g_partial[t] : 0;
    int sc = v;
#pragma unroll
    for (int d = 1; d < 32; d <<= 1) {
        int n = __shfl_up_sync(0xffffffffu, sc, d);
        if (lane >= d) sc += n;
    }
    if (wid == 0 && lane == 31) w0sum = sc;
    __syncthreads();
    if (wid == 1) sc += w0sum;
    if (t < NB) g_partial[t] = sc - v;  // exclusive
}

__global__ void k_scan3() {
    __shared__ int warp_sums[8];
    int t = threadIdx.x, b = blockIdx.x;
    int lane = t & 31, wid = t >> 5;
    int base = b * SCAN_CHUNK + t * 4;
    int v[4];
#pragma unroll
    for (int i = 0; i < 4; i++) v[i] = (base + i < NN) ? g_deg[base + i] : 0;
    int s = v[0] + v[1] + v[2] + v[3];
    int sc = s;
#pragma unroll
    for (int d = 1; d < 32; d <<= 1) {
        int n = __shfl_up_sync(0xffffffffu, sc, d);
        if (lane >= d) sc += n;
    }
    if (lane == 31) warp_sums[wid] = sc;
    __syncthreads();
    if (wid == 0) {
        int ws = (lane < 8) ? warp_sums[lane] : 0;
#pragma unroll
        for (int d = 1; d < 8; d <<= 1) {
            int n = __shfl_up_sync(0xffffffffu, ws, d);
            if (lane >= d) ws += n;
        }
        if (lane < 8) warp_sums[lane] = ws;
    }
    __syncthreads();
    int run = g_partial[b] + (wid ? warp_sums[wid - 1] : 0) + (sc - s);
#pragma unroll
    for (int i = 0; i < 4; i++) {
        int idx = base + i;
        if (idx < NN) {
            g_rowptr[idx] = run;
            g_cursor[idx] = run;
            g_dinv[idx]   = rsqrtf((float)v[i] + 1.0f);
            run += v[i];
        }
    }
    if (b == 0 && t == 0) g_rowptr[NN] = NE;
}

__global__ void k_fill(const int* __restrict__ src,
                       const int* __restrict__ dst) {
    int e = blockIdx.x * blockDim.x + threadIdx.x;
    if (e < NE) {
        int d = dst[e];
        int pos = atomicAdd(&g_cursor[d], 1);
        g_csr[pos] = src[e];
    }
}

// ---------------- tensor-core GEMM ------------------------------------------
// C[NN,64] = A[NN,K] @ W[K,64]; epilogue *dinv[row] -> g_xws fp16.
// Block tile: 128 rows x 64 cols, 8 warps; warp w owns cols w*8..w*8+7.
// A staged fp16 in 64-wide K chunks; W^T staged n-major fp16 (conflict-free).

__device__ __forceinline__ void mma16816(float c[4],
                                         unsigned a0, unsigned a1, unsigned a2, unsigned a3,
                                         unsigned b0, unsigned b1) {
    asm volatile(
        "mma.sync.aligned.m16n8k16.row.col.f32.f16.f16.f32 "
        "{%0,%1,%2,%3}, {%4,%5,%6,%7}, {%8,%9}, {%0,%1,%2,%3};\n"
        : "+f"(c[0]), "+f"(c[1]), "+f"(c[2]), "+f"(c[3])
        : "r"(a0), "r"(a1), "r"(a2), "r"(a3), "r"(b0), "r"(b1));
}

template <int K, bool A_FROM_H1>
__global__ void __launch_bounds__(256)
k_gemm(const float* __restrict__ Aext, const float* __restrict__ W) {
    const int KP = 64 + 8;              // Ah row pitch (halfs)
    const int WP = K + 8;               // Wt row pitch (halfs)
    __shared__ __half Ah[128 * KP];
    __shared__ __half Wt[64 * WP];
    int tid = threadIdx.x;
    int lane = tid & 31, warp = tid >> 5;
    int row0 = blockIdx.x * 128;
    int gid = lane >> 2, tig = lane & 3;
    int n0 = warp * 8;

    // stage W^T fp16 (n-major): Wt[n][k] = W[k][n]
    for (int i = tid; i < K * 64; i += 256) {
        int k = i >> 6, n = i & 63;
        Wt[n * WP + k] = __float2half(W[i]);
    }

    float cacc[8][4];
#pragma unroll
    for (int r = 0; r < 8; r++)
        cacc[r][0] = cacc[r][1] = cacc[r][2] = cacc[r][3] = 0.f;

    const int NCH = K / 64;
#pragma unroll
    for (int ch = 0; ch < NCH; ch++) {
        // stage A chunk (128 rows x 64 cols) fp16
        if (A_FROM_H1) {
            for (int i = tid; i < 128 * 32; i += 256) {
                int r = i >> 5, c = i & 31;
                unsigned v = 0;
                if (row0 + r < NN) v = *(const unsigned*)&g_h1[(row0 + r) * 32 + c];
                *(unsigned*)&Ah[r * KP + c * 2] = v;
            }
        } else {
            for (int i = tid; i < 128 * 16; i += 256) {
                int r = i >> 4, c4 = i & 15;
                float4 v = make_float4(0.f, 0.f, 0.f, 0.f);
                if (row0 + r < NN)
                    v = *(const float4*)&Aext[(size_t)(row0 + r) * K + ch * 64 + c4 * 4];
                __half2 h0 = __floats2half2_rn(v.x, v.y);
                __half2 h1 = __floats2half2_rn(v.z, v.w);
                *(unsigned*)&Ah[r * KP + c4 * 4]     = *(unsigned*)&h0;
                *(unsigned*)&Ah[r * KP + c4 * 4 + 2] = *(unsigned*)&h1;
            }
        }
        __syncthreads();
#pragma unroll
        for (int kk = 0; kk < 4; kk++) {
            int kg = ch * 64 + kk * 16;   // k offset in Wt
            int kl = kk * 16;             // k offset in Ah
            const __half* wb = &Wt[(n0 + gid) * WP + kg + tig * 2];
            unsigned b0 = *(const unsigned*)wb;
            unsigned b1 = *(const unsigned*)(wb + 8);
#pragma unroll
            for (int rt = 0; rt < 8; rt++) {
                const __half* ab = &Ah[(rt * 16 + gid) * KP + kl + tig * 2];
                unsigned a0 = *(const unsigned*)ab;
                unsigned a1 = *(const unsigned*)(ab + 8 * KP);
                unsigned a2 = *(const unsigned*)(ab + 8);
                unsigned a3 = *(const unsigned*)(ab + 8 * KP + 8);
                mma16816(cacc[rt], a0, a1, a2, a3, b0, b1);
            }
        }
        __syncthreads();
    }

    // epilogue: *dinv, fp16 store. c0,c1 -> (row gid, cols n0+tig*2,+1); c2,c3 -> row+8
#pragma unroll
    for (int rt = 0; rt < 8; rt++) {
        int r0 = row0 + rt * 16 + gid;
        int r1 = r0 + 8;
        if (r0 < NN) {
            float dv = g_dinv[r0];
            g_xws[r0 * 32 + n0 / 2 + tig] =
                __floats2half2_rn(cacc[rt][0] * dv, cacc[rt][1] * dv);
        }
        if (r1 < NN) {
            float dv = g_dinv[r1];
            g_xws[r1 * 32 + n0 / 2 + tig] =
                __floats2half2_rn(cacc[rt][2] * dv, cacc[rt][3] * dv);
        }
    }
}

// ---------------- aggregation: warp per dst node ----------------------------
__device__ __forceinline__ void agg_row(int node, int lane, float& a0, float& a1) {
    int beg = g_rowptr[node];
    int end = g_rowptr[node + 1];
    a0 = 0.f; a1 = 0.f;
    for (int base = beg; base < end; base += 32) {
        int idx = base + lane;
        int s_l = (idx < end) ? g_csr[idx] : 0;
        int iters = end - base;
        if (iters > 32) iters = 32;
#pragma unroll 4
        for (int j = 0; j < iters; j++) {
            int s = __shfl_sync(0xffffffffu, s_l, j);
            float2 v = __half22float2(g_xws[s * (HID / 2) + lane]);
            a0 += v.x;
            a1 += v.y;
        }
    }
}

__global__ void k_agg1(const float* __restrict__ b1) {
    int warp = (blockIdx.x * blockDim.x + threadIdx.x) >> 5;
    int lane = threadIdx.x & 31;
    if (warp >= NN) return;
    float a0, a1;
    agg_row(warp, lane, a0, a1);
    float dd = g_dinv[warp];
    float2 sv = __half22float2(g_xws[warp * (HID / 2) + lane]);
    float r0 = fmaxf(fmaf(dd, a0 + sv.x, b1[2 * lane + 0]), 0.f);
    float r1 = fmaxf(fmaf(dd, a1 + sv.y, b1[2 * lane + 1]), 0.f);
    g_h1[warp * (HID / 2) + lane] = __floats2half2_rn(r0, r1);
}

// layer-2 aggregation fused with 64->12 FC + bfc. Writes d_out directly.
__global__ void k_agg2(const float* __restrict__ b2, const float* __restrict__ Wfc,
                       const float* __restrict__ bfc, float* __restrict__ out) {
    __shared__ float sW[HID * NCLS];
    __shared__ float sb2[HID];
    __shared__ float sbfc[NCLS];
    int tid = threadIdx.x;
    for (int i = tid; i < HID * NCLS; i += 256) sW[i] = Wfc[i];
    if (tid < HID)  sb2[tid]  = b2[tid];
    if (tid < NCLS) sbfc[tid] = bfc[tid];
    __syncthreads();

    int warp = (blockIdx.x * blockDim.x + tid) >> 5;
    int lane = tid & 31;
    if (warp >= NN) return;
    float a0, a1;
    agg_row(warp, lane, a0, a1);
    float dd = g_dinv[warp];
    float2 sv = __half22float2(g_xws[warp * (HID / 2) + lane]);
    float t0 = fmaxf(fmaf(dd, a0 + sv.x, sb2[2 * lane + 0]), 0.f);
    float t1 = fmaxf(fmaf(dd, a1 + sv.y, sb2[2 * lane + 1]), 0.f);

    float res = 0.f;
#pragma unroll
    for (int c = 0; c < NCLS; c++) {
        float p = t0 * sW[(2 * lane + 0) * NCLS + c] + t1 * sW[(2 * lane + 1) * NCLS + c];
        p += __shfl_xor_sync(0xffffffffu, p, 16);
        p += __shfl_xor_sync(0xffffffffu, p, 8);
        p += __shfl_xor_sync(0xffffffffu, p, 4);
        p += __shfl_xor_sync(0xffffffffu, p, 2);
        p += __shfl_xor_sync(0xffffffffu, p, 1);
        if (lane == c) res = p + sbfc[c];
    }
    if (lane < NCLS) out[warp * NCLS + lane] = res;
}

// ---------------- launch -----------------------------------------------------
extern "C" void kernel_launch(void* const* d_in, const int* in_sizes, int n_in,
                              void* d_out, int out_size) {
    const float* x   = (const float*)d_in[0];
    const int*   ei  = (const int*)d_in[1];   // int32 (JAX x64-disabled)
    const float* W1  = (const float*)d_in[2];
    const float* b1  = (const float*)d_in[3];
    const float* W2  = (const float*)d_in[4];
    const float* b2  = (const float*)d_in[5];
    const float* Wfc = (const float*)d_in[6];
    const float* bfc = (const float*)d_in[7];
    float* out = (float*)d_out;
    const int* srcp = ei;
    const int* dstp = ei + NE;

    k_zero_deg<<<(NN + 255) / 256, 256>>>();
    k_count<<<(NE + 255) / 256, 256>>>(dstp);
    k_scan1<<<NB, 256>>>();
    k_scan2<<<1, 64>>>();
    k_scan3<<<NB, 256>>>();
    k_fill<<<(NE + 255) / 256, 256>>>(srcp, dstp);

    k_gemm<FEAT, false><<<(NN + 127) / 128, 256>>>(x, W1);     // -> g_xws (fp16)
    k_agg1<<<(NN + 7) / 8, 256>>>(b1);                          // -> g_h1 (fp16)
    k_gemm<HID, true><<<(NN + 127) / 128, 256>>>(nullptr, W2);  // -> g_xws (fp16)
    k_agg2<<<(NN + 7) / 8, 256>>>(b2, Wfc, bfc, out);           // -> d_out
}

// round 6
// speedup vs baseline: 1.2225x; 1.0313x over previous
#include <cuda_runtime.h>
#include <cuda_fp16.h>

#define NN 50000
#define NE 800000
#define FEAT 128
#define HID 64
#define NCLS 12
#define SB 49                         // scan blocks (1024 nodes each)

// ---------------- scratch (static device globals; zero-initialized) ----------
__device__ __align__(16) int     g_deg[NN];                  // zero-invariant
__device__ __align__(16) unsigned long long g_state[SB];     // zero-invariant
__device__ __align__(16) int     g_rowptr[NN + 1];
__device__ __align__(16) int     g_cursor[NN];
__device__ __align__(16) int     g_csr[NE];
__device__ __align__(16) float   g_dinv[NN];
__device__ __align__(16) __half2 g_xws[NN * (HID / 2)];  // (A@W)*dinv fp16, 128B/row
__device__ __align__(16) __half2 g_h1[NN * (HID / 2)];   // layer-1 activations (fp16)

// ---------------- CSR build ---------------------------------------------------
__global__ void k_count(const int* __restrict__ dst) {
    int e = blockIdx.x * blockDim.x + threadIdx.x;
    if (e < NE) atomicAdd(&g_deg[dst[e]], 1);
}

// exclusive block scan over 1024 values (shfl warp scans + smem)
__device__ __forceinline__ int block_excl_scan(int v, int* sm32) {
    int lane = threadIdx.x & 31, wid = threadIdx.x >> 5;
    int incl = v;
#pragma unroll
    for (int d = 1; d < 32; d <<= 1) {
        int n = __shfl_up_sync(0xffffffffu, incl, d);
        if (lane >= d) incl += n;
    }
    if (lane == 31) sm32[wid] = incl;
    __syncthreads();
    if (wid == 0) {
        int w = sm32[lane];
#pragma unroll
        for (int d = 1; d < 32; d <<= 1) {
            int n = __shfl_up_sync(0xffffffffu, w, d);
            if (lane >= d) w += n;
        }
        sm32[lane] = w;
    }
    __syncthreads();
    int off = wid ? sm32[wid - 1] : 0;
    return incl - v + off;
}

// single-pass scan: rowptr/cursor/dinv via decoupled aggregates.
// g_state[b] = (1<<32) | block_total, published once; block b sums states 0..b-1.
__global__ void __launch_bounds__(1024)
k_scan() {
    __shared__ int sm32[32];
    __shared__ int s_base;
    int tid = threadIdx.x, b = blockIdx.x;
    int i = b * 1024 + tid;
    int v = (i < NN) ? g_deg[i] : 0;
    int excl = block_excl_scan(v, sm32);
    if (tid == 1023) {
        unsigned long long st = (1ULL << 32) | (unsigned)(excl + v);
        atomicExch(&g_state[b], st);
    }
    // lookback: warp 0 sums predecessors' aggregates
    if (tid < 32) {
        unsigned sum = 0;
        for (int j = tid; j < b; j += 32) {
            unsigned long long s;
            do { s = atomicAdd(&g_state[j], 0ULL); } while (!(s >> 32));
            sum += (unsigned)s;
        }
#pragma unroll
        for (int d = 16; d; d >>= 1) sum += __shfl_xor_sync(0xffffffffu, sum, d);
        if (tid == 0) s_base = (int)sum;
    }
    __syncthreads();
    if (i < NN) {
        int run = s_base + excl;
        g_rowptr[i] = run;
        g_cursor[i] = run;
        g_dinv[i]   = rsqrtf((float)v + 1.0f);
    }
    if (b == 0 && tid == 0) g_rowptr[NN] = NE;
}

// fill CSR; also restore zero-invariants (g_deg, g_state) for the next replay
__global__ void k_fill(const int* __restrict__ src,
                       const int* __restrict__ dst) {
    int e = blockIdx.x * blockDim.x + threadIdx.x;
    if (e < NN) g_deg[e] = 0;
    if (e < SB) g_state[e] = 0ULL;
    if (e < NE) {
        int d = dst[e];
        int pos = atomicAdd(&g_cursor[d], 1);
        g_csr[pos] = src[e];
    }
}

// ---------------- tensor-core GEMM ------------------------------------------
// C[NN,64] = A[NN,K] @ W[K,64]; epilogue *dinv[row] -> g_xws fp16.
__device__ __forceinline__ void mma16816(float c[4],
                                         unsigned a0, unsigned a1, unsigned a2, unsigned a3,
                                         unsigned b0, unsigned b1) {
    asm volatile(
        "mma.sync.aligned.m16n8k16.row.col.f32.f16.f16.f32 "
        "{%0,%1,%2,%3}, {%4,%5,%6,%7}, {%8,%9}, {%0,%1,%2,%3};\n"
        : "+f"(c[0]), "+f"(c[1]), "+f"(c[2]), "+f"(c[3])
        : "r"(a0), "r"(a1), "r"(a2), "r"(a3), "r"(b0), "r"(b1));
}

template <int K, bool A_FROM_H1>
__global__ void __launch_bounds__(256)
k_gemm(const float* __restrict__ Aext, const float* __restrict__ W) {
    const int KP = 64 + 8;              // Ah row pitch (halfs)
    const int WP = K + 8;               // Wt row pitch (halfs)
    __shared__ __half Ah[128 * KP];
    __shared__ __half Wt[64 * WP];
    int tid = threadIdx.x;
    int lane = tid & 31, warp = tid >> 5;
    int row0 = blockIdx.x * 128;
    int gid = lane >> 2, tig = lane & 3;
    int n0 = warp * 8;

    for (int i = tid; i < K * 64; i += 256) {   // Wt[n][k] = W[k][n]
        int k = i >> 6, n = i & 63;
        Wt[n * WP + k] = __float2half(W[i]);
    }

    float cacc[8][4];
#pragma unroll
    for (int r = 0; r < 8; r++)
        cacc[r][0] = cacc[r][1] = cacc[r][2] = cacc[r][3] = 0.f;

    const int NCH = K / 64;
#pragma unroll
    for (int ch = 0; ch < NCH; ch++) {
        if (A_FROM_H1) {
            for (int i = tid; i < 128 * 32; i += 256) {
                int r = i >> 5, c = i & 31;
                unsigned v = 0;
                if (row0 + r < NN) v = *(const unsigned*)&g_h1[(row0 + r) * 32 + c];
                *(unsigned*)&Ah[r * KP + c * 2] = v;
            }
        } else {
            for (int i = tid; i < 128 * 16; i += 256) {
                int r = i >> 4, c4 = i & 15;
                float4 v = make_float4(0.f, 0.f, 0.f, 0.f);
                if (row0 + r < NN)
                    v = *(const float4*)&Aext[(size_t)(row0 + r) * K + ch * 64 + c4 * 4];
                __half2 h0 = __floats2half2_rn(v.x, v.y);
                __half2 h1 = __floats2half2_rn(v.z, v.w);
                *(unsigned*)&Ah[r * KP + c4 * 4]     = *(unsigned*)&h0;
                *(unsigned*)&Ah[r * KP + c4 * 4 + 2] = *(unsigned*)&h1;
            }
        }
        __syncthreads();
#pragma unroll
        for (int kk = 0; kk < 4; kk++) {
            int kg = ch * 64 + kk * 16;
            int kl = kk * 16;
            const __half* wb = &Wt[(n0 + gid) * WP + kg + tig * 2];
            unsigned b0 = *(const unsigned*)wb;
            unsigned b1 = *(const unsigned*)(wb + 8);
#pragma unroll
            for (int rt = 0; rt < 8; rt++) {
                const __half* ab = &Ah[(rt * 16 + gid) * KP + kl + tig * 2];
                unsigned a0 = *(const unsigned*)ab;
                unsigned a1 = *(const unsigned*)(ab + 8 * KP);
                unsigned a2 = *(const unsigned*)(ab + 8);
                unsigned a3 = *(const unsigned*)(ab + 8 * KP + 8);
                mma16816(cacc[rt], a0, a1, a2, a3, b0, b1);
            }
        }
        __syncthreads();
    }

#pragma unroll
    for (int rt = 0; rt < 8; rt++) {
        int r0 = row0 + rt * 16 + gid;
        int r1 = r0 + 8;
        if (r0 < NN) {
            float dv = g_dinv[r0];
            g_xws[r0 * 32 + n0 / 2 + tig] =
                __floats2half2_rn(cacc[rt][0] * dv, cacc[rt][1] * dv);
        }
        if (r1 < NN) {
            float dv = g_dinv[r1];
            g_xws[r1 * 32 + n0 / 2 + tig] =
                __floats2half2_rn(cacc[rt][2] * dv, cacc[rt][3] * dv);
        }
    }
}

// ---------------- aggregation: warp per dst node ----------------------------
__device__ __forceinline__ void agg_row(int node, int lane, float& a0, float& a1) {
    int beg = g_rowptr[node];
    int end = g_rowptr[node + 1];
    a0 = 0.f; a1 = 0.f;
    for (int base = beg; base < end; base += 32) {
        int idx = base + lane;
        int s_l = (idx < end) ? g_csr[idx] : 0;
        int iters = end - base;
        if (iters > 32) iters = 32;
#pragma unroll 4
        for (int j = 0; j < iters; j++) {
            int s = __shfl_sync(0xffffffffu, s_l, j);
            float2 v = __half22float2(g_xws[s * (HID / 2) + lane]);
            a0 += v.x;
            a1 += v.y;
        }
    }
}

__global__ void k_agg1(const float* __restrict__ b1) {
    int warp = (blockIdx.x * blockDim.x + threadIdx.x) >> 5;
    int lane = threadIdx.x & 31;
    if (warp >= NN) return;
    float a0, a1;
    agg_row(warp, lane, a0, a1);
    float dd = g_dinv[warp];
    float2 sv = __half22float2(g_xws[warp * (HID / 2) + lane]);
    float r0 = fmaxf(fmaf(dd, a0 + sv.x, b1[2 * lane + 0]), 0.f);
    float r1 = fmaxf(fmaf(dd, a1 + sv.y, b1[2 * lane + 1]), 0.f);
    g_h1[warp * (HID / 2) + lane] = __floats2half2_rn(r0, r1);
}

__global__ void k_agg2(const float* __restrict__ b2, const float* __restrict__ Wfc,
                       const float* __restrict__ bfc, float* __restrict__ out) {
    __shared__ float sW[HID * NCLS];
    __shared__ float sb2[HID];
    __shared__ float sbfc[NCLS];
    int tid = threadIdx.x;
    for (int i = tid; i < HID * NCLS; i += 256) sW[i] = Wfc[i];
    if (tid < HID)  sb2[tid]  = b2[tid];
    if (tid < NCLS) sbfc[tid] = bfc[tid];
    __syncthreads();

    int warp = (blockIdx.x * blockDim.x + tid) >> 5;
    int lane = tid & 31;
    if (warp >= NN) return;
    float a0, a1;
    agg_row(warp, lane, a0, a1);
    float dd = g_dinv[warp];
    float2 sv = __half22float2(g_xws[warp * (HID / 2) + lane]);
    float t0 = fmaxf(fmaf(dd, a0 + sv.x, sb2[2 * lane + 0]), 0.f);
    float t1 = fmaxf(fmaf(dd, a1 + sv.y, sb2[2 * lane + 1]), 0.f);

    float res = 0.f;
#pragma unroll
    for (int c = 0; c < NCLS; c++) {
        float p = t0 * sW[(2 * lane + 0) * NCLS + c] + t1 * sW[(2 * lane + 1) * NCLS + c];
        p += __shfl_xor_sync(0xffffffffu, p, 16);
        p += __shfl_xor_sync(0xffffffffu, p, 8);
        p += __shfl_xor_sync(0xffffffffu, p, 4);
        p += __shfl_xor_sync(0xffffffffu, p, 2);
        p += __shfl_xor_sync(0xffffffffu, p, 1);
        if (lane == c) res = p + sbfc[c];
    }
    if (lane < NCLS) out[warp * NCLS + lane] = res;
}

// ---------------- launch -----------------------------------------------------
extern "C" void kernel_launch(void* const* d_in, const int* in_sizes, int n_in,
                              void* d_out, int out_size) {
    const float* x   = (const float*)d_in[0];
    const int*   ei  = (const int*)d_in[1];   // int32 (JAX x64-disabled)
    const float* W1  = (const float*)d_in[2];
    const float* b1  = (const float*)d_in[3];
    const float* W2  = (const float*)d_in[4];
    const float* b2  = (const float*)d_in[5];
    const float* Wfc = (const float*)d_in[6];
    const float* bfc = (const float*)d_in[7];
    float* out = (float*)d_out;
    const int* srcp = ei;
    const int* dstp = ei + NE;

    k_count<<<(NE + 255) / 256, 256>>>(dstp);
    k_scan<<<SB, 1024>>>();
    k_fill<<<(NE + 255) / 256, 256>>>(srcp, dstp);

    k_gemm<FEAT, false><<<(NN + 127) / 128, 256>>>(x, W1);     // -> g_xws (fp16)
    k_agg1<<<(NN + 7) / 8, 256>>>(b1);                          // -> g_h1 (fp16)
    k_gemm<HID, true><<<(NN + 127) / 128, 256>>>(nullptr, W2);  // -> g_xws (fp16)
    k_agg2<<<(NN + 7) / 8, 256>>>(b2, Wfc, bfc, out);           // -> d_out
}

// round 7
// speedup vs baseline: 1.2459x; 1.0191x over previous
#include <cuda_runtime.h>
#include <cuda_fp16.h>

#define NN 50000
#define NE 800000
#define FEAT 128
#define HID 64
#define NCLS 12
#define SB 49                         // scan blocks (1024 nodes each)

// ---------------- scratch (static device globals; zero-initialized) ----------
__device__ __align__(16) int     g_deg[NN];                  // zero-invariant
__device__ __align__(16) unsigned long long g_state[SB];     // zero-invariant
__device__ __align__(16) int     g_rowptr[NN + 1];
__device__ __align__(16) int     g_cursor[NN];
__device__ __align__(16) int     g_csr[NE];
__device__ __align__(16) float   g_dinv[NN];
__device__ __align__(16) __half2 g_xws[NN * (HID / 2)];  // (A@W)*dinv fp16, 128B/row
__device__ __align__(16) __half2 g_h1[NN * (HID / 2)];   // layer-1 activations (fp16)

// ---------------- CSR build ---------------------------------------------------
__global__ void k_count(const int* __restrict__ dst) {
    int e = blockIdx.x * blockDim.x + threadIdx.x;
    if (e < NE) atomicAdd(&g_deg[dst[e]], 1);
}

__device__ __forceinline__ int block_excl_scan(int v, int* sm32) {
    int lane = threadIdx.x & 31, wid = threadIdx.x >> 5;
    int incl = v;
#pragma unroll
    for (int d = 1; d < 32; d <<= 1) {
        int n = __shfl_up_sync(0xffffffffu, incl, d);
        if (lane >= d) incl += n;
    }
    if (lane == 31) sm32[wid] = incl;
    __syncthreads();
    if (wid == 0) {
        int w = sm32[lane];
#pragma unroll
        for (int d = 1; d < 32; d <<= 1) {
            int n = __shfl_up_sync(0xffffffffu, w, d);
            if (lane >= d) w += n;
        }
        sm32[lane] = w;
    }
    __syncthreads();
    int off = wid ? sm32[wid - 1] : 0;
    return incl - v + off;
}

// single-pass scan via decoupled aggregates
__global__ void __launch_bounds__(1024)
k_scan() {
    __shared__ int sm32[32];
    __shared__ int s_base;
    int tid = threadIdx.x, b = blockIdx.x;
    int i = b * 1024 + tid;
    int v = (i < NN) ? g_deg[i] : 0;
    int excl = block_excl_scan(v, sm32);
    if (tid == 1023) {
        unsigned long long st = (1ULL << 32) | (unsigned)(excl + v);
        atomicExch(&g_state[b], st);
    }
    if (tid < 32) {
        unsigned sum = 0;
        for (int j = tid; j < b; j += 32) {
            unsigned long long s;
            do { s = atomicAdd(&g_state[j], 0ULL); } while (!(s >> 32));
            sum += (unsigned)s;
        }
#pragma unroll
        for (int d = 16; d; d >>= 1) sum += __shfl_xor_sync(0xffffffffu, sum, d);
        if (tid == 0) s_base = (int)sum;
    }
    __syncthreads();
    if (i < NN) {
        int run = s_base + excl;
        g_rowptr[i] = run;
        g_cursor[i] = run;
        g_dinv[i]   = rsqrtf((float)v + 1.0f);
    }
    if (b == 0 && tid == 0) g_rowptr[NN] = NE;
}

// fill CSR; restore zero-invariants for the next replay
__global__ void k_fill(const int* __restrict__ src,
                       const int* __restrict__ dst) {
    int e = blockIdx.x * blockDim.x + threadIdx.x;
    if (e < NN) g_deg[e] = 0;
    if (e < SB) g_state[e] = 0ULL;
    if (e < NE) {
        int d = dst[e];
        int pos = atomicAdd(&g_cursor[d], 1);
        g_csr[pos] = src[e];
    }
}

// ---------------- tensor-core GEMM ------------------------------------------
// C[NN,64] = A[NN,K] @ W[K,64]; epilogue *dinv[row] -> g_xws fp16.
// 64-row tiles (grid ~782) for occupancy; register double-buffered A loads.
__device__ __forceinline__ void mma16816(float c[4],
                                         unsigned a0, unsigned a1, unsigned a2, unsigned a3,
                                         unsigned b0, unsigned b1) {
    asm volatile(
        "mma.sync.aligned.m16n8k16.row.col.f32.f16.f16.f32 "
        "{%0,%1,%2,%3}, {%4,%5,%6,%7}, {%8,%9}, {%0,%1,%2,%3};\n"
        : "+f"(c[0]), "+f"(c[1]), "+f"(c[2]), "+f"(c[3])
        : "r"(a0), "r"(a1), "r"(a2), "r"(a3), "r"(b0), "r"(b1));
}

template <int K, bool A_FROM_H1>
__global__ void __launch_bounds__(256)
k_gemm(const float* __restrict__ Aext, const float* __restrict__ W) {
    const int KP = 64 + 8;              // Ah row pitch (halfs)
    const int WP = K + 8;               // Wt row pitch (halfs)
    __shared__ __half Ah[64 * KP];
    __shared__ __half Wt[64 * WP];
    int tid = threadIdx.x;
    int lane = tid & 31, warp = tid >> 5;
    int row0 = blockIdx.x * 64;
    int gid = lane >> 2, tig = lane & 3;
    int n0 = warp * 8;

    for (int i = tid; i < K * 64; i += 256) {   // Wt[n][k] = W[k][n]
        int k = i >> 6, n = i & 63;
        Wt[n * WP + k] = __float2half(W[i]);
    }

    float cacc[4][4];
#pragma unroll
    for (int r = 0; r < 4; r++)
        cacc[r][0] = cacc[r][1] = cacc[r][2] = cacc[r][3] = 0.f;

    const int NCH = K / 64;
    // A-chunk: 64 rows x 64 cols. fp32 path: 4 float4/thread. fp16: 2 uint4/thread? use 8 uint/thread.
    float4  vf[4];     // fp32 staging regs
    unsigned vh[8];    // fp16 staging regs

    // prefetch chunk 0
    if (A_FROM_H1) {
#pragma unroll
        for (int p = 0; p < 8; p++) {
            int i = tid + p * 256;          // i in [0, 2048): r=i>>5, c=i&31
            int r = i >> 5, c = i & 31;
            vh[p] = (row0 + r < NN) ? *(const unsigned*)&g_h1[(row0 + r) * 32 + c] : 0u;
        }
    } else {
#pragma unroll
        for (int p = 0; p < 4; p++) {
            int i = tid + p * 256;          // i in [0, 1024): r=i>>4, c4=i&15
            int r = i >> 4, c4 = i & 15;
            vf[p] = (row0 + r < NN)
                ? *(const float4*)&Aext[(size_t)(row0 + r) * K + c4 * 4]
                : make_float4(0.f, 0.f, 0.f, 0.f);
        }
    }

#pragma unroll
    for (int ch = 0; ch < NCH; ch++) {
        // store staged regs to smem
        if (A_FROM_H1) {
#pragma unroll
            for (int p = 0; p < 8; p++) {
                int i = tid + p * 256;
                int r = i >> 5, c = i & 31;
                *(unsigned*)&Ah[r * KP + c * 2] = vh[p];
            }
        } else {
#pragma unroll
            for (int p = 0; p < 4; p++) {
                int i = tid + p * 256;
                int r = i >> 4, c4 = i & 15;
                __half2 h0 = __floats2half2_rn(vf[p].x, vf[p].y);
                __half2 h1 = __floats2half2_rn(vf[p].z, vf[p].w);
                *(unsigned*)&Ah[r * KP + c4 * 4]     = *(unsigned*)&h0;
                *(unsigned*)&Ah[r * KP + c4 * 4 + 2] = *(unsigned*)&h1;
            }
        }
        __syncthreads();

        // prefetch next chunk while doing MMA on this one
        if (!A_FROM_H1 && ch + 1 < NCH) {
#pragma unroll
            for (int p = 0; p < 4; p++) {
                int i = tid + p * 256;
                int r = i >> 4, c4 = i & 15;
                vf[p] = (row0 + r < NN)
                    ? *(const float4*)&Aext[(size_t)(row0 + r) * K + (ch + 1) * 64 + c4 * 4]
                    : make_float4(0.f, 0.f, 0.f, 0.f);
            }
        }

#pragma unroll
        for (int kk = 0; kk < 4; kk++) {
            int kg = ch * 64 + kk * 16;
            int kl = kk * 16;
            const __half* wb = &Wt[(n0 + gid) * WP + kg + tig * 2];
            unsigned b0 = *(const unsigned*)wb;
            unsigned b1 = *(const unsigned*)(wb + 8);
#pragma unroll
            for (int rt = 0; rt < 4; rt++) {
                const __half* ab = &Ah[(rt * 16 + gid) * KP + kl + tig * 2];
                unsigned a0 = *(const unsigned*)ab;
                unsigned a1 = *(const unsigned*)(ab + 8 * KP);
                unsigned a2 = *(const unsigned*)(ab + 8);
                unsigned a3 = *(const unsigned*)(ab + 8 * KP + 8);
                mma16816(cacc[rt], a0, a1, a2, a3, b0, b1);
            }
        }
        if (ch + 1 < NCH) __syncthreads();
    }

#pragma unroll
    for (int rt = 0; rt < 4; rt++) {
        int r0 = row0 + rt * 16 + gid;
        int r1 = r0 + 8;
        if (r0 < NN) {
            float dv = g_dinv[r0];
            g_xws[r0 * 32 + n0 / 2 + tig] =
                __floats2half2_rn(cacc[rt][0] * dv, cacc[rt][1] * dv);
        }
        if (r1 < NN) {
            float dv = g_dinv[r1];
            g_xws[r1 * 32 + n0 / 2 + tig] =
                __floats2half2_rn(cacc[rt][2] * dv, cacc[rt][3] * dv);
        }
    }
}

// ---------------- aggregation: warp per dst node ----------------------------
__device__ __forceinline__ void agg_row(int node, int lane, float& a0, float& a1) {
    int beg = g_rowptr[node];
    int end = g_rowptr[node + 1];
    a0 = 0.f; a1 = 0.f;
    for (int base = beg; base < end; base += 32) {
        int idx = base + lane;
        int s_l = (idx < end) ? g_csr[idx] : 0;
        int iters = end - base;
        if (iters > 32) iters = 32;
#pragma unroll 4
        for (int j = 0; j < iters; j++) {
            int s = __shfl_sync(0xffffffffu, s_l, j);
            float2 v = __half22float2(g_xws[s * (HID / 2) + lane]);
            a0 += v.x;
            a1 += v.y;
        }
    }
}

__global__ void k_agg1(const float* __restrict__ b1) {
    int warp = (blockIdx.x * blockDim.x + threadIdx.x) >> 5;
    int lane = threadIdx.x & 31;
    if (warp >= NN) return;
    float a0, a1;
    agg_row(warp, lane, a0, a1);
    float dd = g_dinv[warp];
    float2 sv = __half22float2(g_xws[warp * (HID / 2) + lane]);
    float r0 = fmaxf(fmaf(dd, a0 + sv.x, b1[2 * lane + 0]), 0.f);
    float r1 = fmaxf(fmaf(dd, a1 + sv.y, b1[2 * lane + 1]), 0.f);
    g_h1[warp * (HID / 2) + lane] = __floats2half2_rn(r0, r1);
}

__global__ void k_agg2(const float* __restrict__ b2, const float* __restrict__ Wfc,
                       const float* __restrict__ bfc, float* __restrict__ out) {
    __shared__ float sW[HID * NCLS];
    __shared__ float sb2[HID];
    __shared__ float sbfc[NCLS];
    int tid = threadIdx.x;
    for (int i = tid; i < HID * NCLS; i += 256) sW[i] = Wfc[i];
    if (tid < HID)  sb2[tid]  = b2[tid];
    if (tid < NCLS) sbfc[tid] = bfc[tid];
    __syncthreads();

    int warp = (blockIdx.x * blockDim.x + tid) >> 5;
    int lane = tid & 31;
    if (warp >= NN) return;
    float a0, a1;
    agg_row(warp, lane, a0, a1);
    float dd = g_dinv[warp];
    float2 sv = __half22float2(g_xws[warp * (HID / 2) + lane]);
    float t0 = fmaxf(fmaf(dd, a0 + sv.x, sb2[2 * lane + 0]), 0.f);
    float t1 = fmaxf(fmaf(dd, a1 + sv.y, sb2[2 * lane + 1]), 0.f);

    float res = 0.f;
#pragma unroll
    for (int c = 0; c < NCLS; c++) {
        float p = t0 * sW[(2 * lane + 0) * NCLS + c] + t1 * sW[(2 * lane + 1) * NCLS + c];
        p += __shfl_xor_sync(0xffffffffu, p, 16);
        p += __shfl_xor_sync(0xffffffffu, p, 8);
        p += __shfl_xor_sync(0xffffffffu, p, 4);
        p += __shfl_xor_sync(0xffffffffu, p, 2);
        p += __shfl_xor_sync(0xffffffffu, p, 1);
        if (lane == c) res = p + sbfc[c];
    }
    if (lane < NCLS) out[warp * NCLS + lane] = res;
}

// ---------------- launch -----------------------------------------------------
extern "C" void kernel_launch(void* const* d_in, const int* in_sizes, int n_in,
                              void* d_out, int out_size) {
    const float* x   = (const float*)d_in[0];
    const int*   ei  = (const int*)d_in[1];   // int32 (JAX x64-disabled)
    const float* W1  = (const float*)d_in[2];
    const float* b1  = (const float*)d_in[3];
    const float* W2  = (const float*)d_in[4];
    const float* b2  = (const float*)d_in[5];
    const float* Wfc = (const float*)d_in[6];
    const float* bfc = (const float*)d_in[7];
    float* out = (float*)d_out;
    const int* srcp = ei;
    const int* dstp = ei + NE;

    k_count<<<(NE + 255) / 256, 256>>>(dstp);
    k_scan<<<SB, 1024>>>();
    k_fill<<<(NE + 255) / 256, 256>>>(srcp, dstp);

    k_gemm<FEAT, false><<<(NN + 63) / 64, 256>>>(x, W1);      // -> g_xws (fp16)
    k_agg1<<<(NN + 7) / 8, 256>>>(b1);                         // -> g_h1 (fp16)
    k_gemm<HID, true><<<(NN + 63) / 64, 256>>>(nullptr, W2);   // -> g_xws (fp16)
    k_agg2<<<(NN + 7) / 8, 256>>>(b2, Wfc, bfc, out);          // -> d_out
}